// round 12
// baseline (speedup 1.0000x reference)
#include <cuda_runtime.h>
#include <math.h>

// Problem constants
#define NB 8
#define NT 8
#define BT 64
#define NCODE 1024
#define Gd 128
#define CSd 64
#define TAd 256
#define SMAX 96
#define CMAX 64
#define ROWS 32          // rows per kA block
#define UTS2 100         // kBC transposed stride (floats, mult of 4)
#define KREG 80          // Whh rows held in registers in k_lstm
#define KTAIL 48         // Whh rows held in smem (transposed) in k_lstm
#define WTS 52           // transposed tail stride (floats)

// ---------------- fast activations (inf-safe) ----------------
__device__ __forceinline__ float fsig(float x) {
    return 1.f / (1.f + __expf(-x));
}
__device__ __forceinline__ float ftanh(float x) {
    return 1.f - 2.f / (__expf(2.f * x) + 1.f);
}

// ---------------- device scratch ----------------
__device__ float d_EW1[NCODE * Gd];
__device__ float2 d_csr[NCODE * CMAX];
__device__ int    d_ccnt[NCODE];
__device__ int    d_act[BT * SMAX];
__device__ int    d_scnt[BT];
__device__ unsigned char d_rank[BT * NCODE];
__device__ float  d_psum;
__device__ float  d_u[BT * SMAX * Gd];   // Phase A output rows
__device__ float  d_zx[BT * 512];        // visit@Wih + bih + bhh

// ---- GCN edge contribution, g = lane*4 + q layout (LDS.128 on EW1 hits)
__device__ __forceinline__ void edge_contrib(
    int n, float v, int lane,
    const unsigned char* __restrict__ sRank,
    const unsigned char* __restrict__ sCcnt,
    const float* __restrict__ sEW1,
    const float4 bb, float4& acc)
{
    float4 hv = bb;
    int cn = sCcnt[n];
    const float2* rown = d_csr + n * CMAX;
    int g0 = lane * 4;
    int e2 = 0;
    for (; e2 + 4 <= cn; e2 += 4) {
        float2 c0 = rown[e2], c1 = rown[e2 + 1],
               c2 = rown[e2 + 2], c3 = rown[e2 + 3];
        unsigned char r0 = sRank[__float_as_int(c0.x)];
        unsigned char r1 = sRank[__float_as_int(c1.x)];
        unsigned char r2 = sRank[__float_as_int(c2.x)];
        unsigned char r3 = sRank[__float_as_int(c3.x)];
        if (r0 != 0xFF) {
            float4 ew = *reinterpret_cast<const float4*>(&sEW1[(int)r0 * Gd + g0]);
            hv.x += c0.y * ew.x; hv.y += c0.y * ew.y;
            hv.z += c0.y * ew.z; hv.w += c0.y * ew.w;
        }
        if (r1 != 0xFF) {
            float4 ew = *reinterpret_cast<const float4*>(&sEW1[(int)r1 * Gd + g0]);
            hv.x += c1.y * ew.x; hv.y += c1.y * ew.y;
            hv.z += c1.y * ew.z; hv.w += c1.y * ew.w;
        }
        if (r2 != 0xFF) {
            float4 ew = *reinterpret_cast<const float4*>(&sEW1[(int)r2 * Gd + g0]);
            hv.x += c2.y * ew.x; hv.y += c2.y * ew.y;
            hv.z += c2.y * ew.z; hv.w += c2.y * ew.w;
        }
        if (r3 != 0xFF) {
            float4 ew = *reinterpret_cast<const float4*>(&sEW1[(int)r3 * Gd + g0]);
            hv.x += c3.y * ew.x; hv.y += c3.y * ew.y;
            hv.z += c3.y * ew.z; hv.w += c3.y * ew.w;
        }
    }
    for (; e2 < cn; ++e2) {
        float2 c0 = rown[e2];
        unsigned char r0 = sRank[__float_as_int(c0.x)];
        if (r0 != 0xFF) {
            float4 ew = *reinterpret_cast<const float4*>(&sEW1[(int)r0 * Gd + g0]);
            hv.x += c0.y * ew.x; hv.y += c0.y * ew.y;
            hv.z += c0.y * ew.z; hv.w += c0.y * ew.w;
        }
    }
    acc.x += v * fmaxf(hv.x, 0.f);
    acc.y += v * fmaxf(hv.y, 0.f);
    acc.z += v * fmaxf(hv.z, 0.f);
    acc.w += v * fmaxf(hv.w, 0.f);
}

// =========================================================================
// K1: setup — EW1, adj CSR (float4 scan), active lists, prior sum
// =========================================================================
__global__ void __launch_bounds__(128) k_setup(
    const float* __restrict__ adj, const float* __restrict__ code_x,
    const float* __restrict__ prior, const float* __restrict__ c_emb,
    const float* __restrict__ W1)
{
    int blk = blockIdx.x;
    int tid = threadIdx.x;
    int warp = tid >> 5, lane = tid & 31;

    if (blk < NCODE) {
        int n = blk;
        __shared__ float sc[CSd];
        __shared__ int wcnt[4];
        if (tid < CSd) sc[tid] = c_emb[n * CSd + tid];
        __syncthreads();
        float acc = 0.f;
        #pragma unroll 16
        for (int j = 0; j < CSd; ++j) acc += sc[j] * W1[j * Gd + tid];
        d_EW1[n * Gd + tid] = acc;

        const float4* row4 = reinterpret_cast<const float4*>(adj + n * NCODE) + warp * 64;
        float4 v4a = row4[lane];
        float4 v4b = row4[32 + lane];
        float vals[8] = {v4a.x, v4a.y, v4a.z, v4a.w, v4b.x, v4b.y, v4b.z, v4b.w};
        int myoff[8];
        int cnt = 0;
        #pragma unroll
        for (int c = 0; c < 8; ++c) {
            unsigned m = __ballot_sync(0xffffffffu, vals[c] != 0.f);
            myoff[c] = cnt + __popc(m & ((1u << lane) - 1u));
            cnt += __popc(m);
        }
        if (lane == 0) wcnt[warp] = cnt;
        __syncthreads();
        int base = 0;
        for (int w = 0; w < warp; ++w) base += wcnt[w];
        #pragma unroll
        for (int c = 0; c < 8; ++c) {
            if (vals[c] != 0.f) {
                int pos = base + myoff[c];
                int idx = warp * 256 + (c >> 2) * 128 + lane * 4 + (c & 3);
                if (pos < CMAX)
                    d_csr[n * CMAX + pos] =
                        make_float2(__int_as_float(idx), vals[c]);
            }
        }
        if (tid == 0) d_ccnt[n] = min(wcnt[0] + wcnt[1] + wcnt[2] + wcnt[3], CMAX);
    } else if (blk == NCODE) {
        __shared__ float sr[128];
        float s = 0.f;
        for (int i = tid; i < NCODE; i += 128) s += prior[i];
        sr[tid] = s; __syncthreads();
        for (int o = 64; o > 0; o >>= 1) {
            if (tid < o) sr[tid] += sr[tid + o];
            __syncthreads();
        }
        if (tid == 0) d_psum = sr[0];
    } else {
        int bt = blk - (NCODE + 1);
        __shared__ int wcnt2[4];
        for (int i = tid; i < NCODE; i += 128) d_rank[bt * NCODE + i] = 0xFF;
        __syncthreads();
        const float4* row4 = reinterpret_cast<const float4*>(code_x + bt * NCODE) + warp * 64;
        float4 v4a = row4[lane];
        float4 v4b = row4[32 + lane];
        float vals[8] = {v4a.x, v4a.y, v4a.z, v4a.w, v4b.x, v4b.y, v4b.z, v4b.w};
        int myoff[8];
        int cnt = 0;
        #pragma unroll
        for (int c = 0; c < 8; ++c) {
            unsigned m = __ballot_sync(0xffffffffu, vals[c] != 0.f);
            myoff[c] = cnt + __popc(m & ((1u << lane) - 1u));
            cnt += __popc(m);
        }
        if (lane == 0) wcnt2[warp] = cnt;
        __syncthreads();
        int base = 0;
        for (int w = 0; w < warp; ++w) base += wcnt2[w];
        #pragma unroll
        for (int c = 0; c < 8; ++c) {
            if (vals[c] != 0.f) {
                int pos = base + myoff[c];
                int idx = warp * 256 + (c >> 2) * 128 + lane * 4 + (c & 3);
                if (pos < SMAX) {
                    d_act[bt * SMAX + pos] = idx;
                    d_rank[bt * NCODE + idx] = (unsigned char)pos;
                }
            }
        }
        if (tid == 0)
            d_scnt[bt] = min(wcnt2[0] + wcnt2[1] + wcnt2[2] + wcnt2[3], SMAX);
    }
}

// =========================================================================
// K2: kA — sparse GCN rows only. grid (3,64) x 512, 49KB smem -> high occ.
// Writes u rows to d_u (coalesced float4).
// =========================================================================
__global__ void __launch_bounds__(512) kA(const float* __restrict__ b1,
                                          const float* __restrict__ prior)
{
    extern __shared__ float sEW1[];          // [96][128] rank-indexed
    __shared__ unsigned char sRank[NCODE];
    __shared__ unsigned char sCcnt[NCODE];
    __shared__ int sActAll[SMAX];

    int bt = blockIdx.y;
    int bx = blockIdx.x;
    int base = bx * ROWS;
    int tid = threadIdx.x;
    int warp = tid >> 5, lane = tid & 31;
    int S = d_scnt[bt];
    int rows = min(S - base, ROWS);
    if (rows <= 0) return;

    for (int i = tid; i < NCODE; i += 512) {
        sRank[i] = d_rank[bt * NCODE + i];
        sCcnt[i] = (unsigned char)d_ccnt[i];
    }
    if (tid < SMAX) sActAll[tid] = (tid < S) ? d_act[bt * SMAX + tid] : 0;
    __syncthreads();

    {
        float4* dst = reinterpret_cast<float4*>(sEW1);
        for (int idx = tid; idx < S * 32; idx += 512) {
            int r = idx >> 5;
            dst[idx] = reinterpret_cast<const float4*>(d_EW1 + sActAll[r] * Gd)[idx & 31];
        }
    }
    __syncthreads();

    float4 bb = *(reinterpret_cast<const float4*>(b1) + lane);
    for (int mi = warp; mi < rows; mi += 16) {
        int am = sActAll[base + mi];
        int cm = sCcnt[am];
        const float2* rowm = d_csr + am * CMAX;
        float2 cvl = make_float2(0.f, 0.f);
        if (lane < cm) cvl = rowm[lane];
        float4 acc = make_float4(0.f, 0.f, 0.f, 0.f);
        int elim = min(cm, 32);
        for (int e = 0; e < elim; ++e) {
            int n   = __shfl_sync(0xffffffffu, __float_as_int(cvl.x), e);
            float v = __shfl_sync(0xffffffffu, cvl.y, e);
            edge_contrib(n, v, lane, sRank, sCcnt, sEW1, bb, acc);
        }
        for (int e = 32; e < cm; ++e) {   // rare overflow path
            float2 cv = rowm[e];
            edge_contrib(__float_as_int(cv.x), cv.y, lane,
                         sRank, sCcnt, sEW1, bb, acc);
        }
        reinterpret_cast<float4*>(d_u)[(bt * SMAX + base + mi) * 32 + lane] = acc;
    }
}

// =========================================================================
// K3: kBC — per bt: co GEMM + LN residual + logits + full softmax + visit
//           + zx. grid 64 x 512, ~100KB dyn smem.
// layout: sUT[128][UTS2] (u, then residual transposed) | sCo[96][128]
// =========================================================================
__global__ void __launch_bounds__(512) kBC(
    const float* __restrict__ prior,
    const float* __restrict__ W2,  const float* __restrict__ b2,
    const float* __restrict__ Wp,  const float* __restrict__ bp,
    const float* __restrict__ lng, const float* __restrict__ lnb,
    const float* __restrict__ Wc,  const float* __restrict__ bc,
    const float* __restrict__ vc,
    const float* __restrict__ Wih, const float* __restrict__ bih,
    const float* __restrict__ bhh)
{
    extern __shared__ float dyn[];
    float* sUT = dyn;                        // [128][UTS2]
    float* sCo = dyn + 128 * UTS2;           // [96][128]
    __shared__ float sPr[SMAX];
    __shared__ float sRedC[4][4][4];
    __shared__ float sLog[SMAX];
    __shared__ float sE[SMAX];
    __shared__ float sVp[4][Gd];
    __shared__ float sVis[Gd];
    __shared__ float sDen;

    int bt = blockIdx.x;
    int tid = threadIdx.x;
    int warp = tid >> 5, lane = tid & 31;
    int s = tid >> 7, g = tid & 127;
    int wis = warp & 3;
    int S = d_scnt[bt];
    int rowsC = (S + 15) & ~15;

    if (tid < SMAX)
        sPr[tid] = (tid < S) ? prior[d_act[bt * SMAX + tid]] / d_psum : 0.f;

    // ---- load u transposed; zero padding rows ----
    for (int idx = tid; idx < S * Gd; idx += 512) {
        int mi = idx >> 7, gg = idx & 127;
        sUT[gg * UTS2 + mi] = d_u[bt * SMAX * Gd + idx];
    }
    for (int idx = tid; idx < (rowsC - S) * Gd; idx += 512) {
        int mi = S + (idx >> 7), gg = idx & 127;
        sUT[gg * UTS2 + mi] = 0.f;
    }
    __syncthreads();

    // ---- Phase B: co = u @ W2 + b2 (16-row chunks; slot owns 4 rows) ----
    {
        float b2g = b2[g];
        for (int m0 = 0; m0 < rowsC; m0 += 16) {
            float4 acc = make_float4(0.f, 0.f, 0.f, 0.f);
            #pragma unroll 4
            for (int j = 0; j < Gd; ++j) {
                float w = W2[j * Gd + g];
                float4 u = *reinterpret_cast<const float4*>(&sUT[j * UTS2 + m0 + s * 4]);
                acc.x += u.x * w; acc.y += u.y * w;
                acc.z += u.z * w; acc.w += u.w * w;
            }
            sCo[(m0 + s * 4 + 0) * Gd + g] = acc.x + b2g;
            sCo[(m0 + s * 4 + 1) * Gd + g] = acc.y + b2g;
            sCo[(m0 + s * 4 + 2) * Gd + g] = acc.z + b2g;
            sCo[(m0 + s * 4 + 3) * Gd + g] = acc.w + b2g;
        }
    }
    __syncthreads();

    // ---- Phase C: prior modulation + LN + leaky relu residual ----
    {
        float wpv[4], bpv[4], lg[4], lb[4];
        #pragma unroll
        for (int q = 0; q < 4; ++q) {
            int gg = lane + 32 * q;
            wpv[q] = Wp[gg]; bpv[q] = bp[gg]; lg[q] = lng[gg]; lb[q] = lnb[gg];
        }
        for (int mi = warp; mi < S; mi += 16) {
            float p = sPr[mi];
            float co[4], cw[4];
            float sum = 0.f;
            #pragma unroll
            for (int q = 0; q < 4; ++q) {
                co[q] = sCo[mi * Gd + lane + 32 * q];
                cw[q] = co[q] * (p * wpv[q] + bpv[q]);
                sum += cw[q];
            }
            #pragma unroll
            for (int o = 16; o > 0; o >>= 1) sum += __shfl_xor_sync(0xffffffffu, sum, o);
            float mu = sum * (1.f / 128.f);
            float vs = 0.f;
            #pragma unroll
            for (int q = 0; q < 4; ++q) { float d = cw[q] - mu; vs += d * d; }
            #pragma unroll
            for (int o = 16; o > 0; o >>= 1) vs += __shfl_xor_sync(0xffffffffu, vs, o);
            float inv = rsqrtf(vs * (1.f / 128.f) + 1e-5f);
            #pragma unroll
            for (int q = 0; q < 4; ++q) {
                float nv = (cw[q] - mu) * inv * lg[q] + lb[q];
                nv = (nv >= 0.f) ? nv : 0.01f * nv;
                float r = co[q] + nv;
                sCo[mi * Gd + lane + 32 * q] = r;
                sUT[(lane + 32 * q) * UTS2 + mi] = r;
            }
        }
    }
    __syncthreads();

    // ---- Phase C2: logits = tanh(co@Wc + bc) @ vc (16-row chunks) ----
    {
        float bcg = bc[g], vcg = vc[g];
        for (int m0 = 0; m0 < rowsC; m0 += 16) {
            float4 acc = make_float4(0.f, 0.f, 0.f, 0.f);
            #pragma unroll 4
            for (int j = 0; j < Gd; ++j) {
                float w = Wc[j * Gd + g];
                float4 u = *reinterpret_cast<const float4*>(&sUT[j * UTS2 + m0 + s * 4]);
                acc.x += u.x * w; acc.y += u.y * w;
                acc.z += u.z * w; acc.w += u.w * w;
            }
            float tv0 = ftanh(acc.x + bcg) * vcg;
            float tv1 = ftanh(acc.y + bcg) * vcg;
            float tv2 = ftanh(acc.z + bcg) * vcg;
            float tv3 = ftanh(acc.w + bcg) * vcg;
            #pragma unroll
            for (int o = 16; o > 0; o >>= 1) {
                tv0 += __shfl_xor_sync(0xffffffffu, tv0, o);
                tv1 += __shfl_xor_sync(0xffffffffu, tv1, o);
                tv2 += __shfl_xor_sync(0xffffffffu, tv2, o);
                tv3 += __shfl_xor_sync(0xffffffffu, tv3, o);
            }
            if (lane == 0) {
                sRedC[s][wis][0] = tv0; sRedC[s][wis][1] = tv1;
                sRedC[s][wis][2] = tv2; sRedC[s][wis][3] = tv3;
            }
            __syncthreads();
            if (tid < 16) {
                int s2 = tid >> 2, i2 = tid & 3;
                int row = m0 + s2 * 4 + i2;
                if (row < S)
                    sLog[row] = sRedC[s2][0][i2] + sRedC[s2][1][i2] +
                                sRedC[s2][2][i2] + sRedC[s2][3][i2];
            }
            __syncthreads();
        }
    }

    // ---- softmax (bounded logits, no max subtraction) ----
    if (tid < 32) {
        float d = 0.f;
        for (int m = tid; m < S; m += 32) {
            float e = __expf(sLog[m]);
            sE[m] = e;
            d += e;
        }
        #pragma unroll
        for (int o = 16; o > 0; o >>= 1) d += __shfl_xor_sync(0xffffffffu, d, o);
        if (tid == 0) sDen = d;
    }
    __syncthreads();

    // ---- visit = (sum_m e_m * co[m]) / den ----
    {
        float v = 0.f;
        for (int m = s; m < S; m += 4) v += sE[m] * sCo[m * Gd + g];
        sVp[s][g] = v;
    }
    __syncthreads();
    if (tid < Gd)
        sVis[tid] = (sVp[0][tid] + sVp[1][tid] + sVp[2][tid] + sVp[3][tid]) / sDen;
    __syncthreads();

    // ---- zx = visit @ Wih + bih + bhh ----
    {
        int j = tid;
        float z = bih[j] + bhh[j];
        #pragma unroll 8
        for (int k = 0; k < Gd; ++k) z += sVis[k] * Wih[k * 512 + j];
        d_zx[bt * 512 + j] = z;
    }
}

// =========================================================================
// K4: k_lstm — LSTM recurrence + temporal attention + classifier.
// grid 8 x 512.
// =========================================================================
__global__ void __launch_bounds__(512) k_lstm(
    const float* __restrict__ Whh, const float* __restrict__ Wt,
    const float* __restrict__ btv, const float* __restrict__ vt,
    const float* __restrict__ Wcls, const float* __restrict__ bcls,
    float* __restrict__ out)
{
    extern __shared__ float dynl[];
    float* sWT = dynl;                    // [512][WTS]
    float* szx = dynl + 512 * WTS;        // [8][512]
    __shared__ __align__(16) float sh[128];
    __shared__ float sg[512];
    __shared__ float shs[8 * 128];
    __shared__ float sU8[8], sRedT[8][2], sRedF[4];

    int b = blockIdx.x, tid = threadIdx.x;
    int warp = tid >> 5, lane = tid & 31;

    {
        const float4* src = reinterpret_cast<const float4*>(d_zx + b * 4096);
        float4* dst = reinterpret_cast<float4*>(szx);
        dst[tid] = src[tid];
        dst[tid + 512] = src[tid + 512];
    }
    float w[KREG];
    #pragma unroll
    for (int k = 0; k < KREG; ++k) w[k] = Whh[k * 512 + tid];
    #pragma unroll
    for (int kk = 0; kk < KTAIL; ++kk)
        sWT[tid * WTS + kk] = Whh[(KREG + kk) * 512 + tid];
    if (tid < 128) sh[tid] = 0.f;
    float cstate = 0.f;
    __syncthreads();

    for (int t = 0; t < 8; ++t) {
        float z = szx[t * 512 + tid];
        if (t > 0) {
            float a0 = 0.f, a1 = 0.f, a2 = 0.f, a3 = 0.f;
            #pragma unroll
            for (int k4 = 0; k4 < KREG / 4; ++k4) {
                float4 hv = *reinterpret_cast<const float4*>(&sh[k4 * 4]);
                a0 += hv.x * w[k4 * 4 + 0];
                a1 += hv.y * w[k4 * 4 + 1];
                a2 += hv.z * w[k4 * 4 + 2];
                a3 += hv.w * w[k4 * 4 + 3];
            }
            #pragma unroll
            for (int kk = 0; kk < KTAIL; kk += 4) {
                float4 hv = *reinterpret_cast<const float4*>(&sh[KREG + kk]);
                float4 wt = *reinterpret_cast<const float4*>(&sWT[tid * WTS + kk]);
                a0 += hv.x * wt.x; a1 += hv.y * wt.y;
                a2 += hv.z * wt.z; a3 += hv.w * wt.w;
            }
            z += (a0 + a1) + (a2 + a3);
        }
        float a = (tid >= 256 && tid < 384) ? ftanh(z) : fsig(z);
        sg[tid] = a;
        __syncthreads();
        if (tid < 128) {
            float c = sg[tid + 128] * cstate + sg[tid] * sg[tid + 256];
            cstate = c;
            float h = sg[tid + 384] * ftanh(c);
            sh[tid] = h;
            shs[t * 128 + tid] = h;
        }
        __syncthreads();
    }

    {
        int t = tid >> 6, taq = tid & 63;
        const float4* Wt4 = reinterpret_cast<const float4*>(Wt);
        float4 a4 = reinterpret_cast<const float4*>(btv)[taq];
        #pragma unroll 4
        for (int h = 0; h < 128; ++h) {
            float hv = shs[t * 128 + h];
            float4 wv = Wt4[h * 64 + taq];
            a4.x += hv * wv.x; a4.y += hv * wv.y;
            a4.z += hv * wv.z; a4.w += hv * wv.w;
        }
        float4 vt4 = reinterpret_cast<const float4*>(vt)[taq];
        float part = ftanh(a4.x) * vt4.x + ftanh(a4.y) * vt4.y +
                     ftanh(a4.z) * vt4.z + ftanh(a4.w) * vt4.w;
        #pragma unroll
        for (int o = 16; o > 0; o >>= 1) part += __shfl_xor_sync(0xffffffffu, part, o);
        if (lane == 0) sRedT[t][warp & 1] = part;
    }
    __syncthreads();
    if (tid < 8) sU8[tid] = sRedT[tid][0] + sRedT[tid][1];
    __syncthreads();
    if (tid == 0) {
        float mx = -3.0e38f;
        #pragma unroll
        for (int t = 0; t < 8; ++t) mx = fmaxf(mx, sU8[t]);
        float se = 0.f;
        #pragma unroll
        for (int t = 0; t < 8; ++t) { float e = __expf(sU8[t] - mx); sU8[t] = e; se += e; }
        float inv = 1.f / se;
        #pragma unroll
        for (int t = 0; t < 8; ++t) sU8[t] *= inv;
    }
    __syncthreads();

    float partial = 0.f;
    if (tid < 128) {
        float p = 0.f;
        #pragma unroll
        for (int t = 0; t < 8; ++t) p += sU8[t] * shs[t * 128 + tid];
        partial = p * Wcls[tid];
    }
    #pragma unroll
    for (int o = 16; o > 0; o >>= 1) partial += __shfl_xor_sync(0xffffffffu, partial, o);
    if (lane == 0 && warp < 4) sRedF[warp] = partial;
    __syncthreads();
    if (tid == 0) out[b] = sRedF[0] + sRedF[1] + sRedF[2] + sRedF[3] + bcls[0];
}

// =========================================================================
extern "C" void kernel_launch(void* const* d_in, const int* in_sizes, int n_in,
                              void* d_out, int out_size)
{
    const float* code_x = (const float*)d_in[0];
    const float* prior  = (const float*)d_in[4];
    const float* adj    = (const float*)d_in[5];
    const float* c_emb  = (const float*)d_in[6];
    const float* W1     = (const float*)d_in[7];
    const float* b1     = (const float*)d_in[8];
    const float* W2     = (const float*)d_in[9];
    const float* b2     = (const float*)d_in[10];
    const float* Wp     = (const float*)d_in[11];
    const float* bp     = (const float*)d_in[12];
    const float* ln_g   = (const float*)d_in[13];
    const float* ln_b   = (const float*)d_in[14];
    const float* Wc     = (const float*)d_in[15];
    const float* bc     = (const float*)d_in[16];
    const float* vc     = (const float*)d_in[17];
    const float* Wt     = (const float*)d_in[18];
    const float* btv    = (const float*)d_in[19];
    const float* vt     = (const float*)d_in[20];
    const float* Wih    = (const float*)d_in[21];
    const float* Whh    = (const float*)d_in[22];
    const float* bih    = (const float*)d_in[23];
    const float* bhh    = (const float*)d_in[24];
    const float* Wcls   = (const float*)d_in[25];
    const float* bcls   = (const float*)d_in[26];

    const int A_SMEM  = SMAX * Gd * (int)sizeof(float);               // 48 KB
    const int BC_SMEM = (128 * UTS2 + SMAX * Gd) * (int)sizeof(float); // ~98 KB
    const int L_SMEM  = (512 * WTS + 8 * 512) * (int)sizeof(float);

    cudaFuncSetAttribute(kA, cudaFuncAttributeMaxDynamicSharedMemorySize, A_SMEM);
    cudaFuncSetAttribute(kBC, cudaFuncAttributeMaxDynamicSharedMemorySize, BC_SMEM);
    cudaFuncSetAttribute(k_lstm, cudaFuncAttributeMaxDynamicSharedMemorySize, L_SMEM);

    k_setup<<<NCODE + 1 + BT, 128>>>(adj, code_x, prior, c_emb, W1);
    kA<<<dim3(3, BT), 512, A_SMEM>>>(b1, prior);
    kBC<<<BT, 512, BC_SMEM>>>(prior, W2, b2, Wp, bp, ln_g, ln_b,
                              Wc, bc, vc, Wih, bih, bhh);
    k_lstm<<<NB, 512, L_SMEM>>>(Whh, Wt, btv, vt, Wcls, bcls, (float*)d_out);
}

// round 14
// speedup vs baseline: 1.4557x; 1.4557x over previous
#include <cuda_runtime.h>
#include <math.h>

// Problem constants
#define NB 8
#define NT 8
#define BT 64
#define NCODE 1024
#define Gd 128
#define CSd 64
#define TAd 256
#define SMAX 96
#define CMAX 64
#define ROWS 32          // rows per kAC block
#define UTS 36           // padded transposed stride (floats)
#define KREG 80          // Whh rows held in registers in k_lstm
#define KTAIL 48         // Whh rows held in smem (row-major) in k_lstm

// ---------------- fast activations (inf-safe) ----------------
__device__ __forceinline__ float fsig(float x) {
    return 1.f / (1.f + __expf(-x));
}
__device__ __forceinline__ float ftanh(float x) {
    return 1.f - 2.f / (__expf(2.f * x) + 1.f);
}

// ---------------- device scratch ----------------
__device__ float d_EW1[NCODE * Gd];
__device__ float2 d_csr[NCODE * CMAX];
__device__ int    d_ccnt[NCODE];
__device__ int    d_act[BT * SMAX];
__device__ int    d_scnt[BT];
__device__ unsigned char d_rank[BT * NCODE];
__device__ float  d_psum;
__device__ float  d_pnum[BT * 3 * Gd];   // per-(bt, row-block) softmax numerator partials
__device__ float  d_pden[BT * 3];        // per-(bt, row-block) denominator partials

// ---- GCN edge contribution, g = lane*4 + q layout (LDS.128 on EW1 hits)
__device__ __forceinline__ void edge_contrib(
    int n, float v, int lane,
    const unsigned char* __restrict__ sRank,
    const unsigned char* __restrict__ sCcnt,
    const float* __restrict__ sEW1,
    const float4 bb, float4& acc)
{
    float4 hv = bb;
    int cn = sCcnt[n];
    const float2* rown = d_csr + n * CMAX;
    int g0 = lane * 4;
    int e2 = 0;
    for (; e2 + 4 <= cn; e2 += 4) {
        float2 c0 = rown[e2], c1 = rown[e2 + 1],
               c2 = rown[e2 + 2], c3 = rown[e2 + 3];
        unsigned char r0 = sRank[__float_as_int(c0.x)];
        unsigned char r1 = sRank[__float_as_int(c1.x)];
        unsigned char r2 = sRank[__float_as_int(c2.x)];
        unsigned char r3 = sRank[__float_as_int(c3.x)];
        if (r0 != 0xFF) {
            float4 ew = *reinterpret_cast<const float4*>(&sEW1[(int)r0 * Gd + g0]);
            hv.x += c0.y * ew.x; hv.y += c0.y * ew.y;
            hv.z += c0.y * ew.z; hv.w += c0.y * ew.w;
        }
        if (r1 != 0xFF) {
            float4 ew = *reinterpret_cast<const float4*>(&sEW1[(int)r1 * Gd + g0]);
            hv.x += c1.y * ew.x; hv.y += c1.y * ew.y;
            hv.z += c1.y * ew.z; hv.w += c1.y * ew.w;
        }
        if (r2 != 0xFF) {
            float4 ew = *reinterpret_cast<const float4*>(&sEW1[(int)r2 * Gd + g0]);
            hv.x += c2.y * ew.x; hv.y += c2.y * ew.y;
            hv.z += c2.y * ew.z; hv.w += c2.y * ew.w;
        }
        if (r3 != 0xFF) {
            float4 ew = *reinterpret_cast<const float4*>(&sEW1[(int)r3 * Gd + g0]);
            hv.x += c3.y * ew.x; hv.y += c3.y * ew.y;
            hv.z += c3.y * ew.z; hv.w += c3.y * ew.w;
        }
    }
    for (; e2 < cn; ++e2) {
        float2 c0 = rown[e2];
        unsigned char r0 = sRank[__float_as_int(c0.x)];
        if (r0 != 0xFF) {
            float4 ew = *reinterpret_cast<const float4*>(&sEW1[(int)r0 * Gd + g0]);
            hv.x += c0.y * ew.x; hv.y += c0.y * ew.y;
            hv.z += c0.y * ew.z; hv.w += c0.y * ew.w;
        }
    }
    acc.x += v * fmaxf(hv.x, 0.f);
    acc.y += v * fmaxf(hv.y, 0.f);
    acc.z += v * fmaxf(hv.z, 0.f);
    acc.w += v * fmaxf(hv.w, 0.f);
}

// =========================================================================
// K1: setup — EW1, adj CSR (float4 scan), active lists, prior sum,
//     zero partials
// =========================================================================
__global__ void __launch_bounds__(128) k_setup(
    const float* __restrict__ adj, const float* __restrict__ code_x,
    const float* __restrict__ prior, const float* __restrict__ c_emb,
    const float* __restrict__ W1)
{
    int blk = blockIdx.x;
    int tid = threadIdx.x;
    int warp = tid >> 5, lane = tid & 31;

    if (blk < NCODE) {
        int n = blk;
        __shared__ float sc[CSd];
        __shared__ int wcnt[4];
        if (tid < CSd) sc[tid] = c_emb[n * CSd + tid];
        __syncthreads();
        float acc = 0.f;
        #pragma unroll 16
        for (int j = 0; j < CSd; ++j) acc += sc[j] * W1[j * Gd + tid];
        d_EW1[n * Gd + tid] = acc;

        const float4* row4 = reinterpret_cast<const float4*>(adj + n * NCODE) + warp * 64;
        float4 v4a = row4[lane];
        float4 v4b = row4[32 + lane];
        float vals[8] = {v4a.x, v4a.y, v4a.z, v4a.w, v4b.x, v4b.y, v4b.z, v4b.w};
        int myoff[8];
        int cnt = 0;
        #pragma unroll
        for (int c = 0; c < 8; ++c) {
            unsigned m = __ballot_sync(0xffffffffu, vals[c] != 0.f);
            myoff[c] = cnt + __popc(m & ((1u << lane) - 1u));
            cnt += __popc(m);
        }
        if (lane == 0) wcnt[warp] = cnt;
        __syncthreads();
        int base = 0;
        for (int w = 0; w < warp; ++w) base += wcnt[w];
        #pragma unroll
        for (int c = 0; c < 8; ++c) {
            if (vals[c] != 0.f) {
                int pos = base + myoff[c];
                int idx = warp * 256 + (c >> 2) * 128 + lane * 4 + (c & 3);
                if (pos < CMAX)
                    d_csr[n * CMAX + pos] =
                        make_float2(__int_as_float(idx), vals[c]);
            }
        }
        if (tid == 0) d_ccnt[n] = min(wcnt[0] + wcnt[1] + wcnt[2] + wcnt[3], CMAX);
    } else if (blk == NCODE) {
        __shared__ float sr[128];
        float s = 0.f;
        for (int i = tid; i < NCODE; i += 128) s += prior[i];
        sr[tid] = s; __syncthreads();
        for (int o = 64; o > 0; o >>= 1) {
            if (tid < o) sr[tid] += sr[tid + o];
            __syncthreads();
        }
        if (tid == 0) d_psum = sr[0];
    } else {
        int bt = blk - (NCODE + 1);
        __shared__ int wcnt2[4];
        for (int i = tid; i < 3 * Gd; i += 128) d_pnum[bt * 3 * Gd + i] = 0.f;
        if (tid < 3) d_pden[bt * 3 + tid] = 0.f;
        for (int i = tid; i < NCODE; i += 128) d_rank[bt * NCODE + i] = 0xFF;
        __syncthreads();
        const float4* row4 = reinterpret_cast<const float4*>(code_x + bt * NCODE) + warp * 64;
        float4 v4a = row4[lane];
        float4 v4b = row4[32 + lane];
        float vals[8] = {v4a.x, v4a.y, v4a.z, v4a.w, v4b.x, v4b.y, v4b.z, v4b.w};
        int myoff[8];
        int cnt = 0;
        #pragma unroll
        for (int c = 0; c < 8; ++c) {
            unsigned m = __ballot_sync(0xffffffffu, vals[c] != 0.f);
            myoff[c] = cnt + __popc(m & ((1u << lane) - 1u));
            cnt += __popc(m);
        }
        if (lane == 0) wcnt2[warp] = cnt;
        __syncthreads();
        int base = 0;
        for (int w = 0; w < warp; ++w) base += wcnt2[w];
        #pragma unroll
        for (int c = 0; c < 8; ++c) {
            if (vals[c] != 0.f) {
                int pos = base + myoff[c];
                int idx = warp * 256 + (c >> 2) * 128 + lane * 4 + (c & 3);
                if (pos < SMAX) {
                    d_act[bt * SMAX + pos] = idx;
                    d_rank[bt * NCODE + idx] = (unsigned char)pos;
                }
            }
        }
        if (tid == 0)
            d_scnt[bt] = min(wcnt2[0] + wcnt2[1] + wcnt2[2] + wcnt2[3], SMAX);
    }
}

// =========================================================================
// K2: kAC — sparse GCN rows + co GEMM + LN residual + logits + softmax
//           partials. grid (3,64) x 512.
// dyn smem: sUT[128][UTS] (reused as sCoT after Phase B) | sCo[32][128] |
//           sEW1[96][128]
// =========================================================================
__global__ void __launch_bounds__(512) kAC(
    const float* __restrict__ prior, const float* __restrict__ b1,
    const float* __restrict__ W2,  const float* __restrict__ b2,
    const float* __restrict__ Wp,  const float* __restrict__ bp,
    const float* __restrict__ lng, const float* __restrict__ lnb,
    const float* __restrict__ Wc,  const float* __restrict__ bc,
    const float* __restrict__ vc)
{
    extern __shared__ float dyn[];
    float* sUT  = dyn;                       // [128][UTS]; becomes sCoT after B
    float* sCo  = dyn + 128 * UTS;           // [32][128]
    float* sEW1 = sCo + ROWS * Gd;           // [96][128] rank-indexed
    __shared__ unsigned char sRank[NCODE];
    __shared__ unsigned char sCcnt[NCODE];
    __shared__ float sPr[ROWS];
    __shared__ float sRedC[4][4][8];
    __shared__ int sActAll[SMAX];
    __shared__ float sE[ROWS];
    __shared__ float sVp[4][Gd];

    int bt = blockIdx.y;
    int bx = blockIdx.x;
    int base = bx * ROWS;
    int tid = threadIdx.x;
    int warp = tid >> 5, lane = tid & 31;
    int s = tid >> 7, g = tid & 127;
    int wis = warp & 3;
    int S = d_scnt[bt];
    int rows = min(S - base, ROWS);
    if (rows <= 0) return;

    for (int i = tid; i < NCODE; i += 512) {
        sRank[i] = d_rank[bt * NCODE + i];
        sCcnt[i] = (unsigned char)d_ccnt[i];
    }
    if (tid < SMAX) sActAll[tid] = (tid < S) ? d_act[bt * SMAX + tid] : 0;
    if (tid < ROWS)
        sPr[tid] = (tid < rows) ? prior[d_act[bt * SMAX + base + tid]] / d_psum : 0.f;
    __syncthreads();

    // ---- stage active EW1 rows (rank-indexed), float4 ----
    {
        float4* dst = reinterpret_cast<float4*>(sEW1);
        for (int idx = tid; idx < S * 32; idx += 512) {
            int r = idx >> 5;
            dst[idx] = reinterpret_cast<const float4*>(d_EW1 + sActAll[r] * Gd)[idx & 31];
        }
    }
    __syncthreads();

    // ---- Phase A: u rows -> transposed smem; warp-parallel edge fetch;
    //      g = lane*4+q layout (LDS.128 hits) ----
    {
        float4 bb = *(reinterpret_cast<const float4*>(b1) + lane);
        for (int mi = warp; mi < ROWS; mi += 16) {
            if (mi < rows) {
                int am = sActAll[base + mi];
                int cm = sCcnt[am];
                const float2* rowm = d_csr + am * CMAX;
                float2 cvl = make_float2(0.f, 0.f);
                if (lane < cm) cvl = rowm[lane];
                float4 acc = make_float4(0.f, 0.f, 0.f, 0.f);
                int elim = min(cm, 32);
                for (int e = 0; e < elim; ++e) {
                    int n   = __shfl_sync(0xffffffffu, __float_as_int(cvl.x), e);
                    float v = __shfl_sync(0xffffffffu, cvl.y, e);
                    edge_contrib(n, v, lane, sRank, sCcnt, sEW1, bb, acc);
                }
                for (int e = 32; e < cm; ++e) {   // rare overflow path
                    float2 cv = rowm[e];
                    edge_contrib(__float_as_int(cv.x), cv.y, lane,
                                 sRank, sCcnt, sEW1, bb, acc);
                }
                sUT[(lane * 4 + 0) * UTS + mi] = acc.x;
                sUT[(lane * 4 + 1) * UTS + mi] = acc.y;
                sUT[(lane * 4 + 2) * UTS + mi] = acc.z;
                sUT[(lane * 4 + 3) * UTS + mi] = acc.w;
            } else {
                #pragma unroll
                for (int q = 0; q < 4; ++q)
                    sUT[(lane * 4 + q) * UTS + mi] = 0.f;
            }
        }
    }
    __syncthreads();

    // ---- Phase B: co = u @ W2 + b2 ----
    {
        float acc[8];
        #pragma unroll
        for (int i = 0; i < 8; ++i) acc[i] = 0.f;
        #pragma unroll 4
        for (int j = 0; j < Gd; ++j) {
            float w = W2[j * Gd + g];
            float4 u0 = *reinterpret_cast<const float4*>(&sUT[j * UTS + s * 8]);
            float4 u1 = *reinterpret_cast<const float4*>(&sUT[j * UTS + s * 8 + 4]);
            acc[0] += u0.x * w; acc[1] += u0.y * w; acc[2] += u0.z * w; acc[3] += u0.w * w;
            acc[4] += u1.x * w; acc[5] += u1.y * w; acc[6] += u1.z * w; acc[7] += u1.w * w;
        }
        float b2g = b2[g];
        #pragma unroll
        for (int i = 0; i < 8; ++i)
            sCo[(s * 8 + i) * Gd + g] = acc[i] + b2g;
    }
    __syncthreads();

    // ---- Phase C: prior modulation + LN + leaky relu residual ----
    {
        float wpv[4], bpv[4], lg[4], lb[4];
        #pragma unroll
        for (int q = 0; q < 4; ++q) {
            int gg = lane + 32 * q;
            wpv[q] = Wp[gg]; bpv[q] = bp[gg]; lg[q] = lng[gg]; lb[q] = lnb[gg];
        }
        for (int mi = warp; mi < rows; mi += 16) {
            float p = sPr[mi];
            float co[4], cw[4];
            float sum = 0.f;
            #pragma unroll
            for (int q = 0; q < 4; ++q) {
                co[q] = sCo[mi * Gd + lane + 32 * q];
                cw[q] = co[q] * (p * wpv[q] + bpv[q]);
                sum += cw[q];
            }
            #pragma unroll
            for (int o = 16; o > 0; o >>= 1) sum += __shfl_xor_sync(0xffffffffu, sum, o);
            float mu = sum * (1.f / 128.f);
            float vs = 0.f;
            #pragma unroll
            for (int q = 0; q < 4; ++q) { float d = cw[q] - mu; vs += d * d; }
            #pragma unroll
            for (int o = 16; o > 0; o >>= 1) vs += __shfl_xor_sync(0xffffffffu, vs, o);
            float inv = rsqrtf(vs * (1.f / 128.f) + 1e-5f);
            #pragma unroll
            for (int q = 0; q < 4; ++q) {
                float nv = (cw[q] - mu) * inv * lg[q] + lb[q];
                nv = (nv >= 0.f) ? nv : 0.01f * nv;
                float r = co[q] + nv;
                sCo[mi * Gd + lane + 32 * q] = r;
                sUT[(lane + 32 * q) * UTS + mi] = r;
            }
        }
    }
    __syncthreads();

    // ---- Phase C2: logits = tanh(co@Wc + bc) @ vc, then exp (bounded) ----
    {
        float acc[8];
        #pragma unroll
        for (int i = 0; i < 8; ++i) acc[i] = 0.f;
        #pragma unroll 4
        for (int j = 0; j < Gd; ++j) {
            float w = Wc[j * Gd + g];
            float4 u0 = *reinterpret_cast<const float4*>(&sUT[j * UTS + s * 8]);
            float4 u1 = *reinterpret_cast<const float4*>(&sUT[j * UTS + s * 8 + 4]);
            acc[0] += u0.x * w; acc[1] += u0.y * w; acc[2] += u0.z * w; acc[3] += u0.w * w;
            acc[4] += u1.x * w; acc[5] += u1.y * w; acc[6] += u1.z * w; acc[7] += u1.w * w;
        }
        float bcg = bc[g], vcg = vc[g];
        #pragma unroll
        for (int i = 0; i < 8; ++i) {
            float tv = ftanh(acc[i] + bcg) * vcg;
            #pragma unroll
            for (int o = 16; o > 0; o >>= 1)
                tv += __shfl_xor_sync(0xffffffffu, tv, o);
            if (lane == 0) sRedC[s][wis][i] = tv;
        }
        __syncthreads();
        if (tid < 32) {
            int s2 = tid >> 3, i2 = tid & 7;
            int row = s2 * 8 + i2;
            float logit = sRedC[s2][0][i2] + sRedC[s2][1][i2] +
                          sRedC[s2][2][i2] + sRedC[s2][3][i2];
            float e = (row < rows) ? __expf(logit) : 0.f;
            sE[row] = e;
            float d = e;
            #pragma unroll
            for (int o = 16; o > 0; o >>= 1) d += __shfl_xor_sync(0xffffffffu, d, o);
            if (tid == 0) d_pden[bt * 3 + bx] = d;
        }
    }
    __syncthreads();

    // ---- partial softmax numerator ----
    {
        float v = 0.f;
        for (int m = s; m < rows; m += 4) v += sE[m] * sCo[m * Gd + g];
        sVp[s][g] = v;
    }
    __syncthreads();
    if (tid < Gd)
        d_pnum[(bt * 3 + bx) * Gd + tid] =
            sVp[0][tid] + sVp[1][tid] + sVp[2][tid] + sVp[3][tid];
}

// =========================================================================
// K3: k_lstm — visit/zx combine + LSTM recurrence + temporal attention
//              + classifier. grid 8 x 512.
// dyn smem: sWtail[KTAIL][512] (row-major, conflict-free) | szx[8][512]
// =========================================================================
__global__ void __launch_bounds__(512) k_lstm(
    const float* __restrict__ Whh, const float* __restrict__ Wt,
    const float* __restrict__ btv, const float* __restrict__ vt,
    const float* __restrict__ Wcls, const float* __restrict__ bcls,
    const float* __restrict__ Wih, const float* __restrict__ bih,
    const float* __restrict__ bhh, float* __restrict__ out)
{
    extern __shared__ float dynl[];
    float* sWtail = dynl;                 // [KTAIL][512] row-major
    float* szx    = dynl + KTAIL * 512;   // [8][512]
    __shared__ __align__(16) float sh[128];
    __shared__ float sg[512];
    __shared__ float shs[8 * 128];
    __shared__ __align__(16) float svisT[128 * 8];   // [k][t]
    __shared__ float sdinv[8];
    __shared__ float sU8[8], sRedT[8][2], sRedF[4];

    int b = blockIdx.x, tid = threadIdx.x;
    int warp = tid >> 5, lane = tid & 31;

    if (tid < 8) {
        int bt = b * 8 + tid;
        sdinv[tid] = 1.f / (d_pden[bt * 3] + d_pden[bt * 3 + 1] + d_pden[bt * 3 + 2]);
    }
    __syncthreads();
    #pragma unroll
    for (int rep = 0; rep < 2; ++rep) {
        int i = rep * 512 + tid;
        int t = i >> 7, k = i & 127;
        int bt = b * 8 + t;
        const float* pn = d_pnum + bt * 3 * Gd;
        float num = pn[k] + pn[Gd + k] + pn[2 * Gd + k];
        svisT[k * 8 + t] = num * sdinv[t];
    }
    __syncthreads();

    {
        float z[8];
        float bsum = bih[tid] + bhh[tid];
        #pragma unroll
        for (int t = 0; t < 8; ++t) z[t] = bsum;
        #pragma unroll 4
        for (int k = 0; k < Gd; ++k) {
            float wv = Wih[k * 512 + tid];
            float4 v0 = *reinterpret_cast<const float4*>(&svisT[k * 8]);
            float4 v1 = *reinterpret_cast<const float4*>(&svisT[k * 8 + 4]);
            z[0] += wv * v0.x; z[1] += wv * v0.y; z[2] += wv * v0.z; z[3] += wv * v0.w;
            z[4] += wv * v1.x; z[5] += wv * v1.y; z[6] += wv * v1.z; z[7] += wv * v1.w;
        }
        #pragma unroll
        for (int t = 0; t < 8; ++t) szx[t * 512 + tid] = z[t];
    }

    // ---- preload Whh: 80 rows in registers, 48 tail rows row-major in smem
    float w[KREG];
    #pragma unroll
    for (int k = 0; k < KREG; ++k) w[k] = Whh[k * 512 + tid];
    {
        const float4* src = reinterpret_cast<const float4*>(Whh + KREG * 512);
        float4* dst = reinterpret_cast<float4*>(sWtail);
        #pragma unroll
        for (int i = 0; i < KTAIL * 128 / 512; ++i)  // 12
            dst[tid + 512 * i] = src[tid + 512 * i];
    }
    if (tid < 128) sh[tid] = 0.f;
    float cstate = 0.f;
    __syncthreads();

    for (int t = 0; t < 8; ++t) {
        float z = szx[t * 512 + tid];
        if (t > 0) {
            float a0 = 0.f, a1 = 0.f, a2 = 0.f, a3 = 0.f;
            #pragma unroll
            for (int k4 = 0; k4 < KREG / 4; ++k4) {
                float4 hv = *reinterpret_cast<const float4*>(&sh[k4 * 4]);
                a0 += hv.x * w[k4 * 4 + 0];
                a1 += hv.y * w[k4 * 4 + 1];
                a2 += hv.z * w[k4 * 4 + 2];
                a3 += hv.w * w[k4 * 4 + 3];
            }
            #pragma unroll
            for (int kk = 0; kk < KTAIL; kk += 4) {
                float4 hv = *reinterpret_cast<const float4*>(&sh[KREG + kk]);
                a0 += hv.x * sWtail[(kk + 0) * 512 + tid];
                a1 += hv.y * sWtail[(kk + 1) * 512 + tid];
                a2 += hv.z * sWtail[(kk + 2) * 512 + tid];
                a3 += hv.w * sWtail[(kk + 3) * 512 + tid];
            }
            z += (a0 + a1) + (a2 + a3);
        }
        float a = (tid >= 256 && tid < 384) ? ftanh(z) : fsig(z);
        sg[tid] = a;
        __syncthreads();
        if (tid < 128) {
            float c = sg[tid + 128] * cstate + sg[tid] * sg[tid + 256];
            cstate = c;
            float h = sg[tid + 384] * ftanh(c);
            sh[tid] = h;
            shs[t * 128 + tid] = h;
        }
        __syncthreads();
    }

    {
        int t = tid >> 6, taq = tid & 63;
        const float4* Wt4 = reinterpret_cast<const float4*>(Wt);
        float4 a4 = reinterpret_cast<const float4*>(btv)[taq];
        #pragma unroll 4
        for (int h = 0; h < 128; ++h) {
            float hv = shs[t * 128 + h];
            float4 wv = Wt4[h * 64 + taq];
            a4.x += hv * wv.x; a4.y += hv * wv.y;
            a4.z += hv * wv.z; a4.w += hv * wv.w;
        }
        float4 vt4 = reinterpret_cast<const float4*>(vt)[taq];
        float part = ftanh(a4.x) * vt4.x + ftanh(a4.y) * vt4.y +
                     ftanh(a4.z) * vt4.z + ftanh(a4.w) * vt4.w;
        #pragma unroll
        for (int o = 16; o > 0; o >>= 1) part += __shfl_xor_sync(0xffffffffu, part, o);
        if (lane == 0) sRedT[t][warp & 1] = part;
    }
    __syncthreads();
    if (tid < 8) sU8[tid] = sRedT[tid][0] + sRedT[tid][1];
    __syncthreads();
    if (tid == 0) {
        float mx = -3.0e38f;
        #pragma unroll
        for (int t = 0; t < 8; ++t) mx = fmaxf(mx, sU8[t]);
        float se = 0.f;
        #pragma unroll
        for (int t = 0; t < 8; ++t) { float e = __expf(sU8[t] - mx); sU8[t] = e; se += e; }
        float inv = 1.f / se;
        #pragma unroll
        for (int t = 0; t < 8; ++t) sU8[t] *= inv;
    }
    __syncthreads();

    float partial = 0.f;
    if (tid < 128) {
        float p = 0.f;
        #pragma unroll
        for (int t = 0; t < 8; ++t) p += sU8[t] * shs[t * 128 + tid];
        partial = p * Wcls[tid];
    }
    #pragma unroll
    for (int o = 16; o > 0; o >>= 1) partial += __shfl_xor_sync(0xffffffffu, partial, o);
    if (lane == 0 && warp < 4) sRedF[warp] = partial;
    __syncthreads();
    if (tid == 0) out[b] = sRedF[0] + sRedF[1] + sRedF[2] + sRedF[3] + bcls[0];
}

// =========================================================================
extern "C" void kernel_launch(void* const* d_in, const int* in_sizes, int n_in,
                              void* d_out, int out_size)
{
    const float* code_x = (const float*)d_in[0];
    const float* prior  = (const float*)d_in[4];
    const float* adj    = (const float*)d_in[5];
    const float* c_emb  = (const float*)d_in[6];
    const float* W1     = (const float*)d_in[7];
    const float* b1     = (const float*)d_in[8];
    const float* W2     = (const float*)d_in[9];
    const float* b2     = (const float*)d_in[10];
    const float* Wp     = (const float*)d_in[11];
    const float* bp     = (const float*)d_in[12];
    const float* ln_g   = (const float*)d_in[13];
    const float* ln_b   = (const float*)d_in[14];
    const float* Wc     = (const float*)d_in[15];
    const float* bc     = (const float*)d_in[16];
    const float* vc     = (const float*)d_in[17];
    const float* Wt     = (const float*)d_in[18];
    const float* btv    = (const float*)d_in[19];
    const float* vt     = (const float*)d_in[20];
    const float* Wih    = (const float*)d_in[21];
    const float* Whh    = (const float*)d_in[22];
    const float* bih    = (const float*)d_in[23];
    const float* bhh    = (const float*)d_in[24];
    const float* Wcls   = (const float*)d_in[25];
    const float* bcls   = (const float*)d_in[26];

    const int AC_SMEM = (128 * UTS + ROWS * Gd + SMAX * Gd) * (int)sizeof(float);
    const int L_SMEM  = (KTAIL * 512 + 8 * 512) * (int)sizeof(float);

    cudaFuncSetAttribute(kAC, cudaFuncAttributeMaxDynamicSharedMemorySize, AC_SMEM);
    cudaFuncSetAttribute(k_lstm, cudaFuncAttributeMaxDynamicSharedMemorySize, L_SMEM);

    k_setup<<<NCODE + 1 + BT, 128>>>(adj, code_x, prior, c_emb, W1);
    kAC<<<dim3(3, BT), 512, AC_SMEM>>>(
        prior, b1, W2, b2, Wp, bp, ln_g, ln_b, Wc, bc, vc);
    k_lstm<<<NB, 512, L_SMEM>>>(Whh, Wt, btv, vt, Wcls, bcls,
                                Wih, bih, bhh, (float*)d_out);
}

// round 15
// speedup vs baseline: 1.5031x; 1.0326x over previous
#include <cuda_runtime.h>
#include <math.h>

// Problem constants
#define NB 8
#define NT 8
#define BT 64
#define NCODE 1024
#define Gd 128
#define CSd 64
#define TAd 256
#define SMAX 96
#define CMAX 64
#define ROWS 32          // rows per kAC block
#define UTS 36           // padded transposed stride (floats)
#define KREG 80          // Whh rows held in registers in k_lstm
#define KTAIL 48         // Whh rows held in smem (row-major) in k_lstm

// ---------------- fast activations (inf-safe) ----------------
__device__ __forceinline__ float fsig(float x) {
    return 1.f / (1.f + __expf(-x));
}
__device__ __forceinline__ float ftanh(float x) {
    return 1.f - 2.f / (__expf(2.f * x) + 1.f);
}

// ---------------- device scratch ----------------
__device__ float d_EW1[NCODE * Gd];
__device__ float2 d_csr[NCODE * CMAX];
__device__ int    d_ccnt[NCODE];
__device__ int    d_act[BT * SMAX];
__device__ int    d_scnt[BT];
__device__ unsigned char d_rank[BT * NCODE];
__device__ float  d_psum;
__device__ float  d_pnum[BT * 3 * Gd];   // per-(bt, row-block) softmax numerator partials
__device__ float  d_pden[BT * 3];        // per-(bt, row-block) denominator partials
__device__ float  d_zx[BT * 512];        // visit@Wih + bih + bhh

// ---- GCN edge contribution, g = lane*4 + q layout (LDS.128 on EW1 hits)
__device__ __forceinline__ void edge_contrib(
    int n, float v, int lane,
    const unsigned char* __restrict__ sRank,
    const unsigned char* __restrict__ sCcnt,
    const float* __restrict__ sEW1,
    const float4 bb, float4& acc)
{
    float4 hv = bb;
    int cn = sCcnt[n];
    const float2* rown = d_csr + n * CMAX;
    int g0 = lane * 4;
    int e2 = 0;
    for (; e2 + 4 <= cn; e2 += 4) {
        float2 c0 = rown[e2], c1 = rown[e2 + 1],
               c2 = rown[e2 + 2], c3 = rown[e2 + 3];
        unsigned char r0 = sRank[__float_as_int(c0.x)];
        unsigned char r1 = sRank[__float_as_int(c1.x)];
        unsigned char r2 = sRank[__float_as_int(c2.x)];
        unsigned char r3 = sRank[__float_as_int(c3.x)];
        if (r0 != 0xFF) {
            float4 ew = *reinterpret_cast<const float4*>(&sEW1[(int)r0 * Gd + g0]);
            hv.x += c0.y * ew.x; hv.y += c0.y * ew.y;
            hv.z += c0.y * ew.z; hv.w += c0.y * ew.w;
        }
        if (r1 != 0xFF) {
            float4 ew = *reinterpret_cast<const float4*>(&sEW1[(int)r1 * Gd + g0]);
            hv.x += c1.y * ew.x; hv.y += c1.y * ew.y;
            hv.z += c1.y * ew.z; hv.w += c1.y * ew.w;
        }
        if (r2 != 0xFF) {
            float4 ew = *reinterpret_cast<const float4*>(&sEW1[(int)r2 * Gd + g0]);
            hv.x += c2.y * ew.x; hv.y += c2.y * ew.y;
            hv.z += c2.y * ew.z; hv.w += c2.y * ew.w;
        }
        if (r3 != 0xFF) {
            float4 ew = *reinterpret_cast<const float4*>(&sEW1[(int)r3 * Gd + g0]);
            hv.x += c3.y * ew.x; hv.y += c3.y * ew.y;
            hv.z += c3.y * ew.z; hv.w += c3.y * ew.w;
        }
    }
    for (; e2 < cn; ++e2) {
        float2 c0 = rown[e2];
        unsigned char r0 = sRank[__float_as_int(c0.x)];
        if (r0 != 0xFF) {
            float4 ew = *reinterpret_cast<const float4*>(&sEW1[(int)r0 * Gd + g0]);
            hv.x += c0.y * ew.x; hv.y += c0.y * ew.y;
            hv.z += c0.y * ew.z; hv.w += c0.y * ew.w;
        }
    }
    acc.x += v * fmaxf(hv.x, 0.f);
    acc.y += v * fmaxf(hv.y, 0.f);
    acc.z += v * fmaxf(hv.z, 0.f);
    acc.w += v * fmaxf(hv.w, 0.f);
}

// =========================================================================
// K1: setup — EW1, adj CSR (float4 scan), active lists, prior sum,
//     zero partials
// =========================================================================
__global__ void __launch_bounds__(128) k_setup(
    const float* __restrict__ adj, const float* __restrict__ code_x,
    const float* __restrict__ prior, const float* __restrict__ c_emb,
    const float* __restrict__ W1)
{
    int blk = blockIdx.x;
    int tid = threadIdx.x;
    int warp = tid >> 5, lane = tid & 31;

    if (blk < NCODE) {
        int n = blk;
        __shared__ float sc[CSd];
        __shared__ int wcnt[4];
        if (tid < CSd) sc[tid] = c_emb[n * CSd + tid];
        __syncthreads();
        float acc = 0.f;
        #pragma unroll 16
        for (int j = 0; j < CSd; ++j) acc += sc[j] * W1[j * Gd + tid];
        d_EW1[n * Gd + tid] = acc;

        const float4* row4 = reinterpret_cast<const float4*>(adj + n * NCODE) + warp * 64;
        float4 v4a = row4[lane];
        float4 v4b = row4[32 + lane];
        float vals[8] = {v4a.x, v4a.y, v4a.z, v4a.w, v4b.x, v4b.y, v4b.z, v4b.w};
        int myoff[8];
        int cnt = 0;
        #pragma unroll
        for (int c = 0; c < 8; ++c) {
            unsigned m = __ballot_sync(0xffffffffu, vals[c] != 0.f);
            myoff[c] = cnt + __popc(m & ((1u << lane) - 1u));
            cnt += __popc(m);
        }
        if (lane == 0) wcnt[warp] = cnt;
        __syncthreads();
        int base = 0;
        for (int w = 0; w < warp; ++w) base += wcnt[w];
        #pragma unroll
        for (int c = 0; c < 8; ++c) {
            if (vals[c] != 0.f) {
                int pos = base + myoff[c];
                int idx = warp * 256 + (c >> 2) * 128 + lane * 4 + (c & 3);
                if (pos < CMAX)
                    d_csr[n * CMAX + pos] =
                        make_float2(__int_as_float(idx), vals[c]);
            }
        }
        if (tid == 0) d_ccnt[n] = min(wcnt[0] + wcnt[1] + wcnt[2] + wcnt[3], CMAX);
    } else if (blk == NCODE) {
        __shared__ float sr[128];
        float s = 0.f;
        for (int i = tid; i < NCODE; i += 128) s += prior[i];
        sr[tid] = s; __syncthreads();
        for (int o = 64; o > 0; o >>= 1) {
            if (tid < o) sr[tid] += sr[tid + o];
            __syncthreads();
        }
        if (tid == 0) d_psum = sr[0];
    } else {
        int bt = blk - (NCODE + 1);
        __shared__ int wcnt2[4];
        for (int i = tid; i < 3 * Gd; i += 128) d_pnum[bt * 3 * Gd + i] = 0.f;
        if (tid < 3) d_pden[bt * 3 + tid] = 0.f;
        for (int i = tid; i < NCODE; i += 128) d_rank[bt * NCODE + i] = 0xFF;
        __syncthreads();
        const float4* row4 = reinterpret_cast<const float4*>(code_x + bt * NCODE) + warp * 64;
        float4 v4a = row4[lane];
        float4 v4b = row4[32 + lane];
        float vals[8] = {v4a.x, v4a.y, v4a.z, v4a.w, v4b.x, v4b.y, v4b.z, v4b.w};
        int myoff[8];
        int cnt = 0;
        #pragma unroll
        for (int c = 0; c < 8; ++c) {
            unsigned m = __ballot_sync(0xffffffffu, vals[c] != 0.f);
            myoff[c] = cnt + __popc(m & ((1u << lane) - 1u));
            cnt += __popc(m);
        }
        if (lane == 0) wcnt2[warp] = cnt;
        __syncthreads();
        int base = 0;
        for (int w = 0; w < warp; ++w) base += wcnt2[w];
        #pragma unroll
        for (int c = 0; c < 8; ++c) {
            if (vals[c] != 0.f) {
                int pos = base + myoff[c];
                int idx = warp * 256 + (c >> 2) * 128 + lane * 4 + (c & 3);
                if (pos < SMAX) {
                    d_act[bt * SMAX + pos] = idx;
                    d_rank[bt * NCODE + idx] = (unsigned char)pos;
                }
            }
        }
        if (tid == 0)
            d_scnt[bt] = min(wcnt2[0] + wcnt2[1] + wcnt2[2] + wcnt2[3], SMAX);
    }
}

// =========================================================================
// K2: kAC — sparse GCN rows + co GEMM + LN residual + logits + softmax
//           partials. grid (3,64) x 512.
// =========================================================================
__global__ void __launch_bounds__(512) kAC(
    const float* __restrict__ prior, const float* __restrict__ b1,
    const float* __restrict__ W2,  const float* __restrict__ b2,
    const float* __restrict__ Wp,  const float* __restrict__ bp,
    const float* __restrict__ lng, const float* __restrict__ lnb,
    const float* __restrict__ Wc,  const float* __restrict__ bc,
    const float* __restrict__ vc)
{
    extern __shared__ float dyn[];
    float* sUT  = dyn;                       // [128][UTS]; becomes sCoT after B
    float* sCo  = dyn + 128 * UTS;           // [32][128]
    float* sEW1 = sCo + ROWS * Gd;           // [96][128] rank-indexed
    __shared__ unsigned char sRank[NCODE];
    __shared__ unsigned char sCcnt[NCODE];
    __shared__ float sPr[ROWS];
    __shared__ float sRedC[4][4][8];
    __shared__ int sActAll[SMAX];
    __shared__ float sE[ROWS];
    __shared__ float sVp[4][Gd];

    int bt = blockIdx.y;
    int bx = blockIdx.x;
    int base = bx * ROWS;
    int tid = threadIdx.x;
    int warp = tid >> 5, lane = tid & 31;
    int s = tid >> 7, g = tid & 127;
    int wis = warp & 3;
    int S = d_scnt[bt];
    int rows = min(S - base, ROWS);
    if (rows <= 0) return;

    for (int i = tid; i < NCODE; i += 512) {
        sRank[i] = d_rank[bt * NCODE + i];
        sCcnt[i] = (unsigned char)d_ccnt[i];
    }
    if (tid < SMAX) sActAll[tid] = (tid < S) ? d_act[bt * SMAX + tid] : 0;
    if (tid < ROWS)
        sPr[tid] = (tid < rows) ? prior[d_act[bt * SMAX + base + tid]] / d_psum : 0.f;
    __syncthreads();

    // ---- stage active EW1 rows (rank-indexed), float4 ----
    {
        float4* dst = reinterpret_cast<float4*>(sEW1);
        for (int idx = tid; idx < S * 32; idx += 512) {
            int r = idx >> 5;
            dst[idx] = reinterpret_cast<const float4*>(d_EW1 + sActAll[r] * Gd)[idx & 31];
        }
    }
    __syncthreads();

    // ---- Phase A: u rows -> transposed smem; warp-parallel edge fetch ----
    {
        float4 bb = *(reinterpret_cast<const float4*>(b1) + lane);
        for (int mi = warp; mi < ROWS; mi += 16) {
            if (mi < rows) {
                int am = sActAll[base + mi];
                int cm = sCcnt[am];
                const float2* rowm = d_csr + am * CMAX;
                float2 cvl = make_float2(0.f, 0.f);
                if (lane < cm) cvl = rowm[lane];
                float4 acc = make_float4(0.f, 0.f, 0.f, 0.f);
                int elim = min(cm, 32);
                for (int e = 0; e < elim; ++e) {
                    int n   = __shfl_sync(0xffffffffu, __float_as_int(cvl.x), e);
                    float v = __shfl_sync(0xffffffffu, cvl.y, e);
                    edge_contrib(n, v, lane, sRank, sCcnt, sEW1, bb, acc);
                }
                for (int e = 32; e < cm; ++e) {   // rare overflow path
                    float2 cv = rowm[e];
                    edge_contrib(__float_as_int(cv.x), cv.y, lane,
                                 sRank, sCcnt, sEW1, bb, acc);
                }
                sUT[(lane * 4 + 0) * UTS + mi] = acc.x;
                sUT[(lane * 4 + 1) * UTS + mi] = acc.y;
                sUT[(lane * 4 + 2) * UTS + mi] = acc.z;
                sUT[(lane * 4 + 3) * UTS + mi] = acc.w;
            } else {
                #pragma unroll
                for (int q = 0; q < 4; ++q)
                    sUT[(lane * 4 + q) * UTS + mi] = 0.f;
            }
        }
    }
    __syncthreads();

    // ---- Phase B: co = u @ W2 + b2 ----
    {
        float acc[8];
        #pragma unroll
        for (int i = 0; i < 8; ++i) acc[i] = 0.f;
        #pragma unroll 4
        for (int j = 0; j < Gd; ++j) {
            float w = W2[j * Gd + g];
            float4 u0 = *reinterpret_cast<const float4*>(&sUT[j * UTS + s * 8]);
            float4 u1 = *reinterpret_cast<const float4*>(&sUT[j * UTS + s * 8 + 4]);
            acc[0] += u0.x * w; acc[1] += u0.y * w; acc[2] += u0.z * w; acc[3] += u0.w * w;
            acc[4] += u1.x * w; acc[5] += u1.y * w; acc[6] += u1.z * w; acc[7] += u1.w * w;
        }
        float b2g = b2[g];
        #pragma unroll
        for (int i = 0; i < 8; ++i)
            sCo[(s * 8 + i) * Gd + g] = acc[i] + b2g;
    }
    __syncthreads();

    // ---- Phase C: prior modulation + LN + leaky relu residual ----
    {
        float wpv[4], bpv[4], lg[4], lb[4];
        #pragma unroll
        for (int q = 0; q < 4; ++q) {
            int gg = lane + 32 * q;
            wpv[q] = Wp[gg]; bpv[q] = bp[gg]; lg[q] = lng[gg]; lb[q] = lnb[gg];
        }
        for (int mi = warp; mi < rows; mi += 16) {
            float p = sPr[mi];
            float co[4], cw[4];
            float sum = 0.f;
            #pragma unroll
            for (int q = 0; q < 4; ++q) {
                co[q] = sCo[mi * Gd + lane + 32 * q];
                cw[q] = co[q] * (p * wpv[q] + bpv[q]);
                sum += cw[q];
            }
            #pragma unroll
            for (int o = 16; o > 0; o >>= 1) sum += __shfl_xor_sync(0xffffffffu, sum, o);
            float mu = sum * (1.f / 128.f);
            float vs = 0.f;
            #pragma unroll
            for (int q = 0; q < 4; ++q) { float d = cw[q] - mu; vs += d * d; }
            #pragma unroll
            for (int o = 16; o > 0; o >>= 1) vs += __shfl_xor_sync(0xffffffffu, vs, o);
            float inv = rsqrtf(vs * (1.f / 128.f) + 1e-5f);
            #pragma unroll
            for (int q = 0; q < 4; ++q) {
                float nv = (cw[q] - mu) * inv * lg[q] + lb[q];
                nv = (nv >= 0.f) ? nv : 0.01f * nv;
                float r = co[q] + nv;
                sCo[mi * Gd + lane + 32 * q] = r;
                sUT[(lane + 32 * q) * UTS + mi] = r;
            }
        }
    }
    __syncthreads();

    // ---- Phase C2: logits = tanh(co@Wc + bc) @ vc, then exp (bounded) ----
    {
        float acc[8];
        #pragma unroll
        for (int i = 0; i < 8; ++i) acc[i] = 0.f;
        #pragma unroll 4
        for (int j = 0; j < Gd; ++j) {
            float w = Wc[j * Gd + g];
            float4 u0 = *reinterpret_cast<const float4*>(&sUT[j * UTS + s * 8]);
            float4 u1 = *reinterpret_cast<const float4*>(&sUT[j * UTS + s * 8 + 4]);
            acc[0] += u0.x * w; acc[1] += u0.y * w; acc[2] += u0.z * w; acc[3] += u0.w * w;
            acc[4] += u1.x * w; acc[5] += u1.y * w; acc[6] += u1.z * w; acc[7] += u1.w * w;
        }
        float bcg = bc[g], vcg = vc[g];
        #pragma unroll
        for (int i = 0; i < 8; ++i) {
            float tv = ftanh(acc[i] + bcg) * vcg;
            #pragma unroll
            for (int o = 16; o > 0; o >>= 1)
                tv += __shfl_xor_sync(0xffffffffu, tv, o);
            if (lane == 0) sRedC[s][wis][i] = tv;
        }
        __syncthreads();
        if (tid < 32) {
            int s2 = tid >> 3, i2 = tid & 7;
            int row = s2 * 8 + i2;
            float logit = sRedC[s2][0][i2] + sRedC[s2][1][i2] +
                          sRedC[s2][2][i2] + sRedC[s2][3][i2];
            float e = (row < rows) ? __expf(logit) : 0.f;
            sE[row] = e;
            float d = e;
            #pragma unroll
            for (int o = 16; o > 0; o >>= 1) d += __shfl_xor_sync(0xffffffffu, d, o);
            if (tid == 0) d_pden[bt * 3 + bx] = d;
        }
    }
    __syncthreads();

    // ---- partial softmax numerator ----
    {
        float v = 0.f;
        for (int m = s; m < rows; m += 4) v += sE[m] * sCo[m * Gd + g];
        sVp[s][g] = v;
    }
    __syncthreads();
    if (tid < Gd)
        d_pnum[(bt * 3 + bx) * Gd + tid] =
            sVp[0][tid] + sVp[1][tid] + sVp[2][tid] + sVp[3][tid];
}

// =========================================================================
// K3: kZX — combine softmax partials -> visit; zx = visit@Wih + bih + bhh.
// grid 64 x 512 (one block per bt).
// =========================================================================
__global__ void __launch_bounds__(512) kZX(
    const float* __restrict__ Wih, const float* __restrict__ bih,
    const float* __restrict__ bhh)
{
    __shared__ float sVis[Gd];
    int bt = blockIdx.x, tid = threadIdx.x;

    if (tid < Gd) {
        const float* pn = d_pnum + bt * 3 * Gd;
        float den = d_pden[bt * 3] + d_pden[bt * 3 + 1] + d_pden[bt * 3 + 2];
        sVis[tid] = (pn[tid] + pn[Gd + tid] + pn[2 * Gd + tid]) / den;
    }
    __syncthreads();

    {
        int j = tid;
        float z = bih[j] + bhh[j];
        #pragma unroll 8
        for (int k = 0; k < Gd; ++k) z += sVis[k] * Wih[k * 512 + j];
        d_zx[bt * 512 + j] = z;
    }
}

// =========================================================================
// K4: k_lstm — LSTM recurrence + temporal attention + classifier.
// grid 8 x 512. dyn smem: sWtail[KTAIL][512] row-major | szx[8][512]
// =========================================================================
__global__ void __launch_bounds__(512) k_lstm(
    const float* __restrict__ Whh, const float* __restrict__ Wt,
    const float* __restrict__ btv, const float* __restrict__ vt,
    const float* __restrict__ Wcls, const float* __restrict__ bcls,
    float* __restrict__ out)
{
    extern __shared__ float dynl[];
    float* sWtail = dynl;                 // [KTAIL][512] row-major
    float* szx    = dynl + KTAIL * 512;   // [8][512]
    __shared__ __align__(16) float sh[128];
    __shared__ float sg[512];
    __shared__ float shs[8 * 128];
    __shared__ float sU8[8], sRedT[8][2], sRedF[4];

    int b = blockIdx.x, tid = threadIdx.x;
    int warp = tid >> 5, lane = tid & 31;

    {
        const float4* src = reinterpret_cast<const float4*>(d_zx + b * 4096);
        float4* dst = reinterpret_cast<float4*>(szx);
        dst[tid] = src[tid];
        dst[tid + 512] = src[tid + 512];
    }
    float w[KREG];
    #pragma unroll
    for (int k = 0; k < KREG; ++k) w[k] = Whh[k * 512 + tid];
    {
        const float4* src = reinterpret_cast<const float4*>(Whh + KREG * 512);
        float4* dst = reinterpret_cast<float4*>(sWtail);
        #pragma unroll
        for (int i = 0; i < KTAIL * 128 / 512; ++i)  // 12
            dst[tid + 512 * i] = src[tid + 512 * i];
    }
    if (tid < 128) sh[tid] = 0.f;
    float cstate = 0.f;
    __syncthreads();

    for (int t = 0; t < 8; ++t) {
        float z = szx[t * 512 + tid];
        if (t > 0) {
            float a0 = 0.f, a1 = 0.f, a2 = 0.f, a3 = 0.f;
            #pragma unroll
            for (int k4 = 0; k4 < KREG / 4; ++k4) {
                float4 hv = *reinterpret_cast<const float4*>(&sh[k4 * 4]);
                a0 += hv.x * w[k4 * 4 + 0];
                a1 += hv.y * w[k4 * 4 + 1];
                a2 += hv.z * w[k4 * 4 + 2];
                a3 += hv.w * w[k4 * 4 + 3];
            }
            #pragma unroll
            for (int kk = 0; kk < KTAIL; kk += 4) {
                float4 hv = *reinterpret_cast<const float4*>(&sh[KREG + kk]);
                a0 += hv.x * sWtail[(kk + 0) * 512 + tid];
                a1 += hv.y * sWtail[(kk + 1) * 512 + tid];
                a2 += hv.z * sWtail[(kk + 2) * 512 + tid];
                a3 += hv.w * sWtail[(kk + 3) * 512 + tid];
            }
            z += (a0 + a1) + (a2 + a3);
        }
        float a = (tid >= 256 && tid < 384) ? ftanh(z) : fsig(z);
        sg[tid] = a;
        __syncthreads();
        if (tid < 128) {
            float c = sg[tid + 128] * cstate + sg[tid] * sg[tid + 256];
            cstate = c;
            float h = sg[tid + 384] * ftanh(c);
            sh[tid] = h;
            shs[t * 128 + tid] = h;
        }
        __syncthreads();
    }

    {
        int t = tid >> 6, taq = tid & 63;
        const float4* Wt4 = reinterpret_cast<const float4*>(Wt);
        float4 a4 = reinterpret_cast<const float4*>(btv)[taq];
        #pragma unroll 4
        for (int h = 0; h < 128; ++h) {
            float hv = shs[t * 128 + h];
            float4 wv = Wt4[h * 64 + taq];
            a4.x += hv * wv.x; a4.y += hv * wv.y;
            a4.z += hv * wv.z; a4.w += hv * wv.w;
        }
        float4 vt4 = reinterpret_cast<const float4*>(vt)[taq];
        float part = ftanh(a4.x) * vt4.x + ftanh(a4.y) * vt4.y +
                     ftanh(a4.z) * vt4.z + ftanh(a4.w) * vt4.w;
        #pragma unroll
        for (int o = 16; o > 0; o >>= 1) part += __shfl_xor_sync(0xffffffffu, part, o);
        if (lane == 0) sRedT[t][warp & 1] = part;
    }
    __syncthreads();
    if (tid < 8) sU8[tid] = sRedT[tid][0] + sRedT[tid][1];
    __syncthreads();
    if (tid == 0) {
        float mx = -3.0e38f;
        #pragma unroll
        for (int t = 0; t < 8; ++t) mx = fmaxf(mx, sU8[t]);
        float se = 0.f;
        #pragma unroll
        for (int t = 0; t < 8; ++t) { float e = __expf(sU8[t] - mx); sU8[t] = e; se += e; }
        float inv = 1.f / se;
        #pragma unroll
        for (int t = 0; t < 8; ++t) sU8[t] *= inv;
    }
    __syncthreads();

    float partial = 0.f;
    if (tid < 128) {
        float p = 0.f;
        #pragma unroll
        for (int t = 0; t < 8; ++t) p += sU8[t] * shs[t * 128 + tid];
        partial = p * Wcls[tid];
    }
    #pragma unroll
    for (int o = 16; o > 0; o >>= 1) partial += __shfl_xor_sync(0xffffffffu, partial, o);
    if (lane == 0 && warp < 4) sRedF[warp] = partial;
    __syncthreads();
    if (tid == 0) out[b] = sRedF[0] + sRedF[1] + sRedF[2] + sRedF[3] + bcls[0];
}

// =========================================================================
extern "C" void kernel_launch(void* const* d_in, const int* in_sizes, int n_in,
                              void* d_out, int out_size)
{
    const float* code_x = (const float*)d_in[0];
    const float* prior  = (const float*)d_in[4];
    const float* adj    = (const float*)d_in[5];
    const float* c_emb  = (const float*)d_in[6];
    const float* W1     = (const float*)d_in[7];
    const float* b1     = (const float*)d_in[8];
    const float* W2     = (const float*)d_in[9];
    const float* b2     = (const float*)d_in[10];
    const float* Wp     = (const float*)d_in[11];
    const float* bp     = (const float*)d_in[12];
    const float* ln_g   = (const float*)d_in[13];
    const float* ln_b   = (const float*)d_in[14];
    const float* Wc     = (const float*)d_in[15];
    const float* bc     = (const float*)d_in[16];
    const float* vc     = (const float*)d_in[17];
    const float* Wt     = (const float*)d_in[18];
    const float* btv    = (const float*)d_in[19];
    const float* vt     = (const float*)d_in[20];
    const float* Wih    = (const float*)d_in[21];
    const float* Whh    = (const float*)d_in[22];
    const float* bih    = (const float*)d_in[23];
    const float* bhh    = (const float*)d_in[24];
    const float* Wcls   = (const float*)d_in[25];
    const float* bcls   = (const float*)d_in[26];

    const int AC_SMEM = (128 * UTS + ROWS * Gd + SMAX * Gd) * (int)sizeof(float);
    const int L_SMEM  = (KTAIL * 512 + 8 * 512) * (int)sizeof(float);

    cudaFuncSetAttribute(kAC, cudaFuncAttributeMaxDynamicSharedMemorySize, AC_SMEM);
    cudaFuncSetAttribute(k_lstm, cudaFuncAttributeMaxDynamicSharedMemorySize, L_SMEM);

    k_setup<<<NCODE + 1 + BT, 128>>>(adj, code_x, prior, c_emb, W1);
    kAC<<<dim3(3, BT), 512, AC_SMEM>>>(
        prior, b1, W2, b2, Wp, bp, ln_g, ln_b, Wc, bc, vc);
    kZX<<<BT, 512>>>(Wih, bih, bhh);
    k_lstm<<<NB, 512, L_SMEM>>>(Whh, Wt, btv, vt, Wcls, bcls, (float*)d_out);
}